// round 1
// baseline (speedup 1.0000x reference)
#include <cuda_runtime.h>
#include <math.h>

// Problem constants
#define Bb 4
#define Hh 8
#define BHn 32
#define NN 2048
#define Dd 512
#define DHd 64
#define MF 256
#define CK 128
#define NC 16

// Scratch (device globals: allowed; cudaMalloc is not)
__device__ float g_qp[(size_t)BHn * NN * MF];          // 64 MiB
__device__ float g_kp[(size_t)BHn * NN * MF];          // 64 MiB (holds dd-diag, then kp)
__device__ float g_S [(size_t)BHn * NC * MF * DHd];    // 32 MiB
__device__ float g_z [BHn * NC * MF];
__device__ float g_kmax[BHn];

__global__ void init_kernel() {
    if (threadIdx.x < BHn) g_kmax[threadIdx.x] = -1e30f;
}

// ---------------------------------------------------------------------------
// Feature-map kernel. Thread t owns feature t (proj row in 64 registers).
// Processes 4 rows per pass so LDS.128 broadcasts amortize (1 LDS / 4 FMA).
// ---------------------------------------------------------------------------
template <bool IS_Q>
__global__ void __launch_bounds__(256) feat_kernel(const float* __restrict__ xin,
                                                   const float* __restrict__ proj) {
    __shared__ float xrow[4][64];
    __shared__ float xsq[4][64];
    __shared__ float red[4][8];
    __shared__ float diag_s[4];
    __shared__ float bred[8];

    const int t = threadIdx.x;
    const int bh = blockIdx.y;
    const int b = bh >> 3, h = bh & 7;
    const int n0 = blockIdx.x * 128;
    const int wid = t >> 5, lane = t & 31;

    // proj row -> registers (one-time, L2-cached)
    float pr[64];
#pragma unroll
    for (int i = 0; i < 16; i++) {
        float4 p4 = ((const float4*)proj)[t * 16 + i];
        pr[4 * i + 0] = p4.x; pr[4 * i + 1] = p4.y;
        pr[4 * i + 2] = p4.z; pr[4 * i + 3] = p4.w;
    }

    const float normalizer = 0.35355339059327373f; // 64^-0.25
    float kmaxloc = -1e30f;
    float* outbuf = IS_Q ? g_qp : g_kp;

    for (int rr = 0; rr < 128; rr += 4) {
        {
            int r = t >> 6, d = t & 63;
            float v = xin[((size_t)(b * NN + n0 + rr + r)) * Dd + h * DHd + d];
            xrow[r][d] = v;
            xsq[r][d] = v * v;
        }
        __syncthreads();

        if (wid < 4) { // diag = ||x||^2 / 16
            float s = xsq[wid][lane] + xsq[wid][lane + 32];
#pragma unroll
            for (int off = 16; off; off >>= 1) s += __shfl_down_sync(0xffffffffu, s, off);
            if (lane == 0) diag_s[wid] = s * 0.0625f;
        }

        float dd[4] = {0.f, 0.f, 0.f, 0.f};
#pragma unroll
        for (int d4 = 0; d4 < 16; d4++) {
#pragma unroll
            for (int r = 0; r < 4; r++) {
                float4 x4 = ((const float4*)xrow[r])[d4];
                dd[r] += x4.x * pr[4 * d4 + 0] + x4.y * pr[4 * d4 + 1]
                       + x4.z * pr[4 * d4 + 2] + x4.w * pr[4 * d4 + 3];
            }
        }
#pragma unroll
        for (int r = 0; r < 4; r++) dd[r] *= normalizer;

        if (IS_Q) {
#pragma unroll
            for (int r = 0; r < 4; r++) {
                float m = dd[r];
#pragma unroll
                for (int off = 16; off; off >>= 1)
                    m = fmaxf(m, __shfl_xor_sync(0xffffffffu, m, off));
                if (lane == 0) red[r][wid] = m;
            }
            __syncthreads();
#pragma unroll
            for (int r = 0; r < 4; r++) {
                float m = red[r][0];
#pragma unroll
                for (int w = 1; w < 8; w++) m = fmaxf(m, red[r][w]);
                float val = 0.0625f * (expf(dd[r] - diag_s[r] - m) + 1e-4f);
                outbuf[((size_t)(bh * NN + n0 + rr + r)) * MF + t] = val;
            }
            __syncthreads();
        } else {
            __syncthreads();
#pragma unroll
            for (int r = 0; r < 4; r++) {
                outbuf[((size_t)(bh * NN + n0 + rr + r)) * MF + t] = dd[r] - diag_s[r];
                kmaxloc = fmaxf(kmaxloc, dd[r]);
            }
            __syncthreads();
        }
    }

    if (!IS_Q) {
        float m = kmaxloc;
#pragma unroll
        for (int off = 16; off; off >>= 1)
            m = fmaxf(m, __shfl_xor_sync(0xffffffffu, m, off));
        if (lane == 0) bred[wid] = m;
        __syncthreads();
        if (t == 0) {
            for (int w = 1; w < 8; w++) m = fmaxf(m, bred[w]);
            int* addr = (int*)&g_kmax[bh];
            int old = *addr;
            while (__int_as_float(old) < m) {
                int assumed = old;
                old = atomicCAS(addr, assumed, __float_as_int(m));
                if (old == assumed) break;
            }
        }
    }
}

// kp = ratio * (exp((dd - diag) - max_bh) + 1e-4), elementwise (float4)
__global__ void __launch_bounds__(256) kexp_kernel() {
    size_t i = (size_t)blockIdx.x * 256 + threadIdx.x; // float4 index
    int bh = (int)(i >> 17);                           // 131072 float4 per bh
    float m = g_kmax[bh];
    float4* p = ((float4*)g_kp) + i;
    float4 v = *p;
    v.x = 0.0625f * (expf(v.x - m) + 1e-4f);
    v.y = 0.0625f * (expf(v.y - m) + 1e-4f);
    v.z = 0.0625f * (expf(v.z - m) + 1e-4f);
    v.w = 0.0625f * (expf(v.w - m) + 1e-4f);
    *p = v;
}

// ---------------------------------------------------------------------------
// Per-chunk local KV state: S_local[m][e] = sum_j K[j][m] V[j][e], z = colsum K.
// Thread handles 4 features x 16 e-values (3.2 FMA per smem float loaded).
// ---------------------------------------------------------------------------
__global__ void __launch_bounds__(256) chunk_kv_kernel(const float* __restrict__ vin) {
    __shared__ float4 Vs[128 * 16];
    const int t = threadIdx.x;
    const int c = blockIdx.x, bh = blockIdx.y;
    const int b = bh >> 3, h = bh & 7;
    const int n0 = c * CK;

#pragma unroll
    for (int k = 0; k < 8; k++) {
        int idx = t + k * 256;
        int j = idx >> 4, e4 = idx & 15;
        Vs[idx] = ((const float4*)(vin + ((size_t)(b * NN + n0 + j)) * Dd + h * DHd))[e4];
    }
    __syncthreads();

    const int e4base = (t & 3) * 4; // 4 float4 = 16 e-values
    const int mq = t >> 2;          // 0..63
    float acc[4][16];
    float zacc[4] = {0.f, 0.f, 0.f, 0.f};
#pragma unroll
    for (int q = 0; q < 4; q++)
#pragma unroll
        for (int i = 0; i < 16; i++) acc[q][i] = 0.f;

    const float* kbase = g_kp + (size_t)(bh * NN + n0) * MF;
    for (int j = 0; j < CK; j++) {
        float kv[4];
#pragma unroll
        for (int q = 0; q < 4; q++) kv[q] = kbase[(size_t)j * MF + mq + 64 * q];
        float4 v4[4];
#pragma unroll
        for (int i = 0; i < 4; i++) v4[i] = Vs[j * 16 + e4base + i];
#pragma unroll
        for (int q = 0; q < 4; q++) {
            zacc[q] += kv[q];
#pragma unroll
            for (int i = 0; i < 4; i++) {
                acc[q][4 * i + 0] += kv[q] * v4[i].x;
                acc[q][4 * i + 1] += kv[q] * v4[i].y;
                acc[q][4 * i + 2] += kv[q] * v4[i].z;
                acc[q][4 * i + 3] += kv[q] * v4[i].w;
            }
        }
    }

    float* Sp = g_S + (size_t)(bh * NC + c) * MF * DHd;
    const int e0 = (t & 3) * 16;
#pragma unroll
    for (int q = 0; q < 4; q++) {
        int m = mq + 64 * q;
        float4* dst = (float4*)(Sp + (size_t)m * DHd + e0);
#pragma unroll
        for (int i = 0; i < 4; i++)
            dst[i] = make_float4(acc[q][4 * i + 0], acc[q][4 * i + 1],
                                 acc[q][4 * i + 2], acc[q][4 * i + 3]);
        if ((t & 3) == 0) g_z[(bh * NC + c) * MF + m] = zacc[q];
    }
}

// In-place exclusive prefix over chunks of S and z (per bh).
__global__ void __launch_bounds__(256) prefix_kernel() {
    const int bh = blockIdx.x;
    const int t = threadIdx.x;
    float acc[64];
#pragma unroll
    for (int i = 0; i < 64; i++) acc[i] = 0.f;
    float* Sb = g_S + (size_t)bh * NC * MF * DHd;
    for (int c = 0; c < NC; c++) {
        float* Sc = Sb + (size_t)c * MF * DHd;
#pragma unroll
        for (int i = 0; i < 64; i++) {
            float tmp = Sc[i * 256 + t];
            Sc[i * 256 + t] = acc[i];
            acc[i] += tmp;
        }
    }
    float za = 0.f;
    float* zb = g_z + bh * NC * MF;
    for (int c = 0; c < NC; c++) {
        float tmp = zb[c * MF + t];
        zb[c * MF + t] = za;
        za += tmp;
    }
}

// ---------------------------------------------------------------------------
// Output kernel: per (bh, chunk):
//   A = tril(Q K^T); out = (Q S_prev + A V) * (1/denom)
//   denom_i = q_i.(z_prev+1e-6) + rowsum(A)_i
// ---------------------------------------------------------------------------
#define PA 129  // AsT pitch (scalar stores, tril-masked)
#define PQ 132  // transposed Q/K pitch (float4 aligned)
#define PS 68   // S tile pitch

// smem float offsets
#define OFF_AST 0
#define OFF_QST 16512
#define OFF_KST 24960
#define OFF_VS  33408
#define OFF_ZS  41600
#define OFF_DEN 41856
#define OFF_DIV 42112
#define SMEM_FLOATS 42240

__global__ void __launch_bounds__(256) out_kernel(const float* __restrict__ vin,
                                                  float* __restrict__ outp) {
    extern __shared__ float sm[];
    float* AsT = sm + OFF_AST;
    float* QsT = sm + OFF_QST;
    float* KsT = sm + OFF_KST;
    float* Ss  = KsT; // aliased (phase 3)
    float* Vs  = sm + OFF_VS;
    float* zs  = sm + OFF_ZS;
    float* den2 = sm + OFF_DEN;
    float* dinv = sm + OFF_DIV;

    const int t = threadIdx.x;
    const int c = blockIdx.x, bh = blockIdx.y;
    const int b = bh >> 3, h = bh & 7;
    const int n0 = c * CK;
    const float* qbase = g_qp + (size_t)(bh * NN + n0) * MF;
    const float* kbase = g_kp + (size_t)(bh * NN + n0) * MF;

    // Load V tile and z_prev
#pragma unroll
    for (int k = 0; k < 8; k++) {
        int idx = t + k * 256;
        int j = idx >> 4, e4 = idx & 15;
        ((float4*)Vs)[idx] =
            ((const float4*)(vin + ((size_t)(b * NN + n0 + j)) * Dd + h * DHd))[e4];
    }
    zs[t] = g_z[(bh * NC + c) * MF + t];

    // ---- Phase A: A = Q K^T (M-tiles of 64), 16x16 threads x 8x8 regs ----
    const int tx = t & 15, ty = t >> 4;
    float accA[8][8];
#pragma unroll
    for (int i = 0; i < 8; i++)
#pragma unroll
        for (int j = 0; j < 8; j++) accA[i][j] = 0.f;

    for (int mt = 0; mt < 4; mt++) {
#pragma unroll
        for (int k = 0; k < 8; k++) {
            int idx = t + k * 256;
            int r = idx >> 4, mv = idx & 15;
            float4 q4 = ((const float4*)(qbase + (size_t)r * MF + mt * 64))[mv];
            QsT[(mv * 4 + 0) * PQ + r] = q4.x;
            QsT[(mv * 4 + 1) * PQ + r] = q4.y;
            QsT[(mv * 4 + 2) * PQ + r] = q4.z;
            QsT[(mv * 4 + 3) * PQ + r] = q4.w;
            float4 k4 = ((const float4*)(kbase + (size_t)r * MF + mt * 64))[mv];
            KsT[(mv * 4 + 0) * PQ + r] = k4.x;
            KsT[(mv * 4 + 1) * PQ + r] = k4.y;
            KsT[(mv * 4 + 2) * PQ + r] = k4.z;
            KsT[(mv * 4 + 3) * PQ + r] = k4.w;
        }
        __syncthreads();
#pragma unroll 4
        for (int kk = 0; kk < 64; kk++) {
            float4 a0 = *(const float4*)(QsT + kk * PQ + ty * 8);
            float4 a1 = *(const float4*)(QsT + kk * PQ + ty * 8 + 4);
            float4 b0 = *(const float4*)(KsT + kk * PQ + tx * 8);
            float4 b1 = *(const float4*)(KsT + kk * PQ + tx * 8 + 4);
            float av[8] = {a0.x, a0.y, a0.z, a0.w, a1.x, a1.y, a1.z, a1.w};
            float bv[8] = {b0.x, b0.y, b0.z, b0.w, b1.x, b1.y, b1.z, b1.w};
#pragma unroll
            for (int i = 0; i < 8; i++)
#pragma unroll
                for (int j = 0; j < 8; j++) accA[i][j] += av[i] * bv[j];
        }
        __syncthreads();
    }

    // Store tril-masked A transposed: AsT[col][row]
    const int R = ty * 8, Cg = tx * 8;
#pragma unroll
    for (int jj = 0; jj < 8; jj++) {
        int j = Cg + jj;
#pragma unroll
        for (int ii = 0; ii < 8; ii++) {
            int i = R + ii;
            AsT[j * PA + i] = (j <= i) ? accA[ii][jj] : 0.f;
        }
    }
    __syncthreads();

    // ---- Denominator: q.(z_prev+1e-6) + rowsum(A) ----
    {
        int i = t >> 1, h2 = t & 1;
        float s = 0.f;
        const float* qr = qbase + (size_t)i * MF + h2 * 128;
        const float* zr = zs + h2 * 128;
#pragma unroll 8
        for (int mm = 0; mm < 128; mm += 4) {
            float4 q4 = *(const float4*)(qr + mm);
            s += q4.x * (zr[mm + 0] + 1e-6f) + q4.y * (zr[mm + 1] + 1e-6f)
               + q4.z * (zr[mm + 2] + 1e-6f) + q4.w * (zr[mm + 3] + 1e-6f);
        }
        const float* Ar = AsT + i;
        for (int j = h2 * 64; j < h2 * 64 + 64; j++) s += Ar[j * PA];
        den2[t] = s;
    }
    __syncthreads();
    if (t < 128) dinv[t] = 1.0f / (den2[2 * t] + den2[2 * t + 1]);

    // ---- Phase 3: out = Q S_prev + A V ----
    const int tx2 = t & 7, ty2 = t >> 3;
    float acc2[4][8];
#pragma unroll
    for (int i = 0; i < 4; i++)
#pragma unroll
        for (int j = 0; j < 8; j++) acc2[i][j] = 0.f;

    // GEMM2: Q @ S_prev (K = 256 in 4 tiles)
    for (int mt = 0; mt < 4; mt++) {
#pragma unroll
        for (int k = 0; k < 8; k++) {
            int idx = t + k * 256;
            int r = idx >> 4, mv = idx & 15;
            float4 q4 = ((const float4*)(qbase + (size_t)r * MF + mt * 64))[mv];
            QsT[(mv * 4 + 0) * PQ + r] = q4.x;
            QsT[(mv * 4 + 1) * PQ + r] = q4.y;
            QsT[(mv * 4 + 2) * PQ + r] = q4.z;
            QsT[(mv * 4 + 3) * PQ + r] = q4.w;
        }
#pragma unroll
        for (int k = 0; k < 4; k++) {
            int idx = t + k * 256;
            int mm = idx >> 4, e4 = idx & 15;
            float4 s4 = ((const float4*)(g_S + ((size_t)(bh * NC + c) * MF + mt * 64 + mm) * DHd))[e4];
            ((float4*)(Ss + mm * PS))[e4] = s4;
        }
        __syncthreads();
#pragma unroll 4
        for (int mm = 0; mm < 64; mm++) {
            float4 a4 = *(const float4*)(QsT + mm * PQ + ty2 * 4);
            float4 b0 = *(const float4*)(Ss + mm * PS + tx2 * 8);
            float4 b1 = *(const float4*)(Ss + mm * PS + tx2 * 8 + 4);
            float av[4] = {a4.x, a4.y, a4.z, a4.w};
            float bv[8] = {b0.x, b0.y, b0.z, b0.w, b1.x, b1.y, b1.z, b1.w};
#pragma unroll
            for (int i = 0; i < 4; i++)
#pragma unroll
                for (int j = 0; j < 8; j++) acc2[i][j] += av[i] * bv[j];
        }
        __syncthreads();
    }

    // GEMM1: A @ V (K = 128)
#pragma unroll 2
    for (int j = 0; j < 128; j++) {
        float av[4];
#pragma unroll
        for (int i = 0; i < 4; i++) av[i] = AsT[j * PA + ty2 * 4 + i];
        float4 v0 = *(const float4*)(Vs + j * DHd + tx2 * 8);
        float4 v1 = *(const float4*)(Vs + j * DHd + tx2 * 8 + 4);
        float bv[8] = {v0.x, v0.y, v0.z, v0.w, v1.x, v1.y, v1.z, v1.w};
#pragma unroll
        for (int i = 0; i < 4; i++)
#pragma unroll
            for (int jn = 0; jn < 8; jn++) acc2[i][jn] += av[i] * bv[jn];
    }

    // Epilogue
#pragma unroll
    for (int i = 0; i < 4; i++) {
        int r = ty2 * 4 + i;
        float di = dinv[r];
        float4 o0 = make_float4(acc2[i][0] * di, acc2[i][1] * di,
                                acc2[i][2] * di, acc2[i][3] * di);
        float4 o1 = make_float4(acc2[i][4] * di, acc2[i][5] * di,
                                acc2[i][6] * di, acc2[i][7] * di);
        float4* dst = (float4*)(outp + ((size_t)(b * NN + n0 + r)) * Dd + h * DHd + tx2 * 8);
        dst[0] = o0;
        dst[1] = o1;
    }
}

// ---------------------------------------------------------------------------
extern "C" void kernel_launch(void* const* d_in, const int* in_sizes, int n_in,
                              void* d_out, int out_size) {
    (void)in_sizes; (void)n_in; (void)out_size;
    const float* q    = (const float*)d_in[0];
    const float* k    = (const float*)d_in[1];
    const float* v    = (const float*)d_in[2];
    const float* proj = (const float*)d_in[3];
    float* out = (float*)d_out;

    cudaFuncSetAttribute(out_kernel, cudaFuncAttributeMaxDynamicSharedMemorySize,
                         SMEM_FLOATS * (int)sizeof(float));

    init_kernel<<<1, 32>>>();
    feat_kernel<true><<<dim3(16, 32), 256>>>(q, proj);
    feat_kernel<false><<<dim3(16, 32), 256>>>(k, proj);
    kexp_kernel<<<16384, 256>>>();
    chunk_kv_kernel<<<dim3(16, 32), 256>>>(v);
    prefix_kernel<<<32, 256>>>();
    out_kernel<<<dim3(16, 32), 256, SMEM_FLOATS * (int)sizeof(float)>>>(v, out);
}

// round 3
// speedup vs baseline: 1.1723x; 1.1723x over previous
#include <cuda_runtime.h>
#include <math.h>
#include <stdint.h>

// Problem constants
#define Bb 4
#define Hh 8
#define BHn 32
#define NN 2048
#define Dd 512
#define DHd 64
#define MF 256
#define CK 128
#define NC 16

// Scratch
__device__ float g_qp[(size_t)BHn * NN * MF];          // 64 MiB
__device__ float g_kp[(size_t)BHn * NN * MF];          // 64 MiB
__device__ float g_S [(size_t)BHn * NC * MF * DHd];    // 32 MiB
__device__ float g_z [BHn * NC * MF];
__device__ float g_kmax[BHn];

__device__ __forceinline__ float tf32r(float x) {
    uint32_t u = __float_as_uint(x);
    u = (u + 0x1000u) & 0xFFFFE000u;
    return __uint_as_float(u);
}
__device__ __forceinline__ uint32_t tf32u(float x) {
    return (__float_as_uint(x) + 0x1000u) & 0xFFFFE000u;
}

// Warp-level tf32 MMA (portable ISA, sm_80+; executes on tensor pipe)
__device__ __forceinline__ void mma16n8k8(float c[4], const uint32_t a[4],
                                          const uint32_t b[2]) {
    asm volatile(
        "mma.sync.aligned.m16n8k8.row.col.f32.tf32.tf32.f32 "
        "{%0,%1,%2,%3}, {%4,%5,%6,%7}, {%8,%9}, {%0,%1,%2,%3};"
        : "+f"(c[0]), "+f"(c[1]), "+f"(c[2]), "+f"(c[3])
        : "r"(a[0]), "r"(a[1]), "r"(a[2]), "r"(a[3]), "r"(b[0]), "r"(b[1]));
}

__global__ void init_kernel() {
    if (threadIdx.x < BHn) g_kmax[threadIdx.x] = -1e30f;
}

// ---------------------------------------------------------------------------
// Feature-map kernel (unchanged)
// ---------------------------------------------------------------------------
template <bool IS_Q>
__global__ void __launch_bounds__(256) feat_kernel(const float* __restrict__ xin,
                                                   const float* __restrict__ proj) {
    __shared__ float xrow[4][64];
    __shared__ float xsq[4][64];
    __shared__ float red[4][8];
    __shared__ float diag_s[4];
    __shared__ float bred[8];

    const int t = threadIdx.x;
    const int bh = blockIdx.y;
    const int b = bh >> 3, h = bh & 7;
    const int n0 = blockIdx.x * 128;
    const int wid = t >> 5, lane = t & 31;

    float pr[64];
#pragma unroll
    for (int i = 0; i < 16; i++) {
        float4 p4 = ((const float4*)proj)[t * 16 + i];
        pr[4 * i + 0] = p4.x; pr[4 * i + 1] = p4.y;
        pr[4 * i + 2] = p4.z; pr[4 * i + 3] = p4.w;
    }

    const float normalizer = 0.35355339059327373f;
    float kmaxloc = -1e30f;
    float* outbuf = IS_Q ? g_qp : g_kp;

    for (int rr = 0; rr < 128; rr += 4) {
        {
            int r = t >> 6, d = t & 63;
            float v = xin[((size_t)(b * NN + n0 + rr + r)) * Dd + h * DHd + d];
            xrow[r][d] = v;
            xsq[r][d] = v * v;
        }
        __syncthreads();

        if (wid < 4) {
            float s = xsq[wid][lane] + xsq[wid][lane + 32];
#pragma unroll
            for (int off = 16; off; off >>= 1) s += __shfl_down_sync(0xffffffffu, s, off);
            if (lane == 0) diag_s[wid] = s * 0.0625f;
        }

        float dd[4] = {0.f, 0.f, 0.f, 0.f};
#pragma unroll
        for (int d4 = 0; d4 < 16; d4++) {
#pragma unroll
            for (int r = 0; r < 4; r++) {
                float4 x4 = ((const float4*)xrow[r])[d4];
                dd[r] += x4.x * pr[4 * d4 + 0] + x4.y * pr[4 * d4 + 1]
                       + x4.z * pr[4 * d4 + 2] + x4.w * pr[4 * d4 + 3];
            }
        }
#pragma unroll
        for (int r = 0; r < 4; r++) dd[r] *= normalizer;

        if (IS_Q) {
#pragma unroll
            for (int r = 0; r < 4; r++) {
                float m = dd[r];
#pragma unroll
                for (int off = 16; off; off >>= 1)
                    m = fmaxf(m, __shfl_xor_sync(0xffffffffu, m, off));
                if (lane == 0) red[r][wid] = m;
            }
            __syncthreads();
#pragma unroll
            for (int r = 0; r < 4; r++) {
                float m = red[r][0];
#pragma unroll
                for (int w = 1; w < 8; w++) m = fmaxf(m, red[r][w]);
                float val = 0.0625f * (expf(dd[r] - diag_s[r] - m) + 1e-4f);
                outbuf[((size_t)(bh * NN + n0 + rr + r)) * MF + t] = val;
            }
            __syncthreads();
        } else {
            __syncthreads();
#pragma unroll
            for (int r = 0; r < 4; r++) {
                outbuf[((size_t)(bh * NN + n0 + rr + r)) * MF + t] = dd[r] - diag_s[r];
                kmaxloc = fmaxf(kmaxloc, dd[r]);
            }
            __syncthreads();
        }
    }

    if (!IS_Q) {
        float m = kmaxloc;
#pragma unroll
        for (int off = 16; off; off >>= 1)
            m = fmaxf(m, __shfl_xor_sync(0xffffffffu, m, off));
        if (lane == 0) bred[wid] = m;
        __syncthreads();
        if (t == 0) {
            for (int w = 1; w < 8; w++) m = fmaxf(m, bred[w]);
            int* addr = (int*)&g_kmax[bh];
            int old = *addr;
            while (__int_as_float(old) < m) {
                int assumed = old;
                old = atomicCAS(addr, assumed, __float_as_int(m));
                if (old == assumed) break;
            }
        }
    }
}

__global__ void __launch_bounds__(256) kexp_kernel() {
    size_t i = (size_t)blockIdx.x * 256 + threadIdx.x;
    int bh = (int)(i >> 17);
    float m = g_kmax[bh];
    float4* p = ((float4*)g_kp) + i;
    float4 v = *p;
    v.x = 0.0625f * (expf(v.x - m) + 1e-4f);
    v.y = 0.0625f * (expf(v.y - m) + 1e-4f);
    v.z = 0.0625f * (expf(v.z - m) + 1e-4f);
    v.w = 0.0625f * (expf(v.w - m) + 1e-4f);
    *p = v;
}

// ---------------------------------------------------------------------------
// Per-chunk local KV state (unchanged)
// ---------------------------------------------------------------------------
__global__ void __launch_bounds__(256) chunk_kv_kernel(const float* __restrict__ vin) {
    __shared__ float4 Vs[128 * 16];
    const int t = threadIdx.x;
    const int c = blockIdx.x, bh = blockIdx.y;
    const int b = bh >> 3, h = bh & 7;
    const int n0 = c * CK;

#pragma unroll
    for (int k = 0; k < 8; k++) {
        int idx = t + k * 256;
        int j = idx >> 4, e4 = idx & 15;
        Vs[idx] = ((const float4*)(vin + ((size_t)(b * NN + n0 + j)) * Dd + h * DHd))[e4];
    }
    __syncthreads();

    const int e4base = (t & 3) * 4;
    const int mq = t >> 2;
    float acc[4][16];
    float zacc[4] = {0.f, 0.f, 0.f, 0.f};
#pragma unroll
    for (int q = 0; q < 4; q++)
#pragma unroll
        for (int i = 0; i < 16; i++) acc[q][i] = 0.f;

    const float* kbase = g_kp + (size_t)(bh * NN + n0) * MF;
    for (int j = 0; j < CK; j++) {
        float kv[4];
#pragma unroll
        for (int q = 0; q < 4; q++) kv[q] = kbase[(size_t)j * MF + mq + 64 * q];
        float4 v4[4];
#pragma unroll
        for (int i = 0; i < 4; i++) v4[i] = Vs[j * 16 + e4base + i];
#pragma unroll
        for (int q = 0; q < 4; q++) {
            zacc[q] += kv[q];
#pragma unroll
            for (int i = 0; i < 4; i++) {
                acc[q][4 * i + 0] += kv[q] * v4[i].x;
                acc[q][4 * i + 1] += kv[q] * v4[i].y;
                acc[q][4 * i + 2] += kv[q] * v4[i].z;
                acc[q][4 * i + 3] += kv[q] * v4[i].w;
            }
        }
    }

    float* Sp = g_S + (size_t)(bh * NC + c) * MF * DHd;
    const int e0 = (t & 3) * 16;
#pragma unroll
    for (int q = 0; q < 4; q++) {
        int m = mq + 64 * q;
        float4* dst = (float4*)(Sp + (size_t)m * DHd + e0);
#pragma unroll
        for (int i = 0; i < 4; i++)
            dst[i] = make_float4(acc[q][4 * i + 0], acc[q][4 * i + 1],
                                 acc[q][4 * i + 2], acc[q][4 * i + 3]);
        if ((t & 3) == 0) g_z[(bh * NC + c) * MF + m] = zacc[q];
    }
}

// In-place exclusive prefix over chunks of S and z (per bh).
__global__ void __launch_bounds__(256) prefix_kernel() {
    const int bh = blockIdx.x;
    const int t = threadIdx.x;
    float acc[64];
#pragma unroll
    for (int i = 0; i < 64; i++) acc[i] = 0.f;
    float* Sb = g_S + (size_t)bh * NC * MF * DHd;
    for (int c = 0; c < NC; c++) {
        float* Sc = Sb + (size_t)c * MF * DHd;
#pragma unroll
        for (int i = 0; i < 64; i++) {
            float tmp = Sc[i * 256 + t];
            Sc[i * 256 + t] = acc[i];
            acc[i] += tmp;
        }
    }
    float za = 0.f;
    float* zb = g_z + bh * NC * MF;
    for (int c = 0; c < NC; c++) {
        float tmp = zb[c * MF + t];
        zb[c * MF + t] = za;
        za += tmp;
    }
}

// ---------------------------------------------------------------------------
// Output kernel on warp-level tf32 mma.sync (m16n8k8).
// Fragment-native smem layouts:
//   Afrag tile (16m x 8k) = 32 lanes * uint4 (a0,a1,a2,a3) = 512B
//   Bfrag tile (8k x 8n)  = 32 lanes * uint2 (b0,b1)       = 256B
// bufQ: Q as Afrag (8 mtiles x 32 ktiles) = 128KB, later reused for masked A
//       as Afrag (8 mtiles x 16 ktiles) = first 64KB.
// bufB: 32KB rotating Bfrag buffer (K chunks, S halves, V).
// ---------------------------------------------------------------------------
#define OUT_DSMEM (163840)

__global__ void __launch_bounds__(256) out_kernel(const float* __restrict__ vin,
                                                  float* __restrict__ outp) {
    extern __shared__ float sm[];
    float* bufQ = sm;            // 32768 floats (128KB)
    float* bufB = sm + 32768;    // 8192 floats (32KB)
    __shared__ float zs[256];
    __shared__ float den[128];
    __shared__ float den2[256];
    __shared__ float dinv[128];

    const int t = threadIdx.x, wid = t >> 5, lane = t & 31;
    const int wm = wid >> 2, wn = wid & 3;   // phase-1 warp grid 2x4 (64x32 tiles)
    const int c = blockIdx.x, bh = blockIdx.y;
    const int b = bh >> 3, h = bh & 7;
    const int n0 = c * CK;
    const float* qbase = g_qp + (size_t)(bh * NN + n0) * MF;
    const float* kbase = g_kp + (size_t)(bh * NN + n0) * MF;
    const float* Sbase = g_S + (size_t)(bh * NC + c) * MF * DHd;

    zs[t] = g_z[(bh * NC + c) * MF + t];

    // ---- Stage Q as Afrag: 256 tiles (8 m x 32 k), one tile per warp/iter ----
    {
        const int g = lane >> 2, tq = lane & 3;
#pragma unroll 4
        for (int it = 0; it < 32; it++) {
            int tile = it * 8 + wid;
            int tm = tile >> 5, tk = tile & 31;
            const float* qp = qbase + (size_t)(tm * 16 + g) * MF + tk * 8 + tq;
            uint4 u;
            u.x = tf32u(qp[0]);
            u.y = tf32u(qp[8 * MF]);
            u.z = tf32u(qp[4]);
            u.w = tf32u(qp[8 * MF + 4]);
            ((uint4*)bufQ)[tile * 32 + lane] = u;
        }
    }
    __syncthreads();

    // ---- den init: q . (z_prev + 1e-6) ----
    {
        int i = t >> 1, hf = t & 1;
        float s = 0.f;
        const float* qr = qbase + (size_t)i * MF + hf * 128;
        const float* zr = zs + hf * 128;
#pragma unroll 8
        for (int m = 0; m < 128; m += 4) {
            float4 q4 = *(const float4*)(qr + m);
            s += q4.x * (zr[m + 0] + 1e-6f) + q4.y * (zr[m + 1] + 1e-6f)
               + q4.z * (zr[m + 2] + 1e-6f) + q4.w * (zr[m + 3] + 1e-6f);
        }
        den2[t] = s;
    }
    __syncthreads();
    if (t < 128) den[t] = den2[2 * t] + den2[2 * t + 1];

    // ---- Phase 1: A = Q K^T (128x128, K=256 in 4 chunks of 64) ----
    float accA[4][4][4];
#pragma unroll
    for (int i = 0; i < 4; i++)
#pragma unroll
        for (int j = 0; j < 4; j++)
#pragma unroll
            for (int s = 0; s < 4; s++) accA[i][j][s] = 0.f;

    const int g = lane >> 2, tq = lane & 3;
    for (int kc = 0; kc < 4; kc++) {
        __syncthreads();
        // stage K chunk as Bfrag: 8 ktiles x 16 ntiles
#pragma unroll 2
        for (int it = 0; it < 16; it++) {
            int tile = it * 8 + wid;
            int tk = tile >> 4, tn = tile & 15;
            const float* kp = kbase + (size_t)(tn * 8 + g) * MF + kc * 64 + tk * 8 + tq;
            uint2 u;
            u.x = tf32u(kp[0]);
            u.y = tf32u(kp[4]);
            ((uint2*)bufB)[tile * 32 + lane] = u;
        }
        __syncthreads();
#pragma unroll
        for (int ks = 0; ks < 8; ks++) {
            uint4 af[4];
            uint2 bf[4];
#pragma unroll
            for (int mt = 0; mt < 4; mt++)
                af[mt] = ((const uint4*)bufQ)[((wm * 4 + mt) * 32 + kc * 8 + ks) * 32 + lane];
#pragma unroll
            for (int nt = 0; nt < 4; nt++)
                bf[nt] = ((const uint2*)bufB)[(ks * 16 + wn * 4 + nt) * 32 + lane];
#pragma unroll
            for (int mt = 0; mt < 4; mt++)
#pragma unroll
                for (int nt = 0; nt < 4; nt++)
                    mma16n8k8(accA[mt][nt], (const uint32_t*)&af[mt],
                              (const uint32_t*)&bf[nt]);
        }
    }

    // ---- Mask tril + rowsum -> den (atomic) ----
#pragma unroll
    for (int mt = 0; mt < 4; mt++) {
        int r0 = wm * 64 + mt * 16 + g;
        float rs0 = 0.f, rs1 = 0.f;
#pragma unroll
        for (int nt = 0; nt < 4; nt++) {
            int cb = wn * 32 + nt * 8 + tq * 2;
            float v0 = (cb     <= r0    ) ? accA[mt][nt][0] : 0.f;
            float v1 = (cb + 1 <= r0    ) ? accA[mt][nt][1] : 0.f;
            float v2 = (cb     <= r0 + 8) ? accA[mt][nt][2] : 0.f;
            float v3 = (cb + 1 <= r0 + 8) ? accA[mt][nt][3] : 0.f;
            accA[mt][nt][0] = v0; accA[mt][nt][1] = v1;
            accA[mt][nt][2] = v2; accA[mt][nt][3] = v3;
            rs0 += v0 + v1;
            rs1 += v2 + v3;
        }
        rs0 += __shfl_xor_sync(0xffffffffu, rs0, 1);
        rs0 += __shfl_xor_sync(0xffffffffu, rs0, 2);
        rs1 += __shfl_xor_sync(0xffffffffu, rs1, 1);
        rs1 += __shfl_xor_sync(0xffffffffu, rs1, 2);
        if (tq == 0) {
            atomicAdd(&den[r0], rs0);
            atomicAdd(&den[r0 + 8], rs1);
        }
    }
    __syncthreads();
    if (t < 128) dinv[t] = 1.0f / den[t];

    // ---- Phase 2: out = Q . S_prev (K=256 in 2 halves) ----
    float acc2[4][2][4];
#pragma unroll
    for (int i = 0; i < 4; i++)
#pragma unroll
        for (int j = 0; j < 2; j++)
#pragma unroll
            for (int s = 0; s < 4; s++) acc2[i][j][s] = 0.f;

    for (int hs = 0; hs < 2; hs++) {
        __syncthreads();
        // stage S half as Bfrag: 16 ktiles x 8 ntiles
#pragma unroll 2
        for (int it = 0; it < 16; it++) {
            int tile = it * 8 + wid;
            int tk = tile >> 3, tn = tile & 7;
            const float* sp = Sbase + (size_t)(hs * 128 + tk * 8 + tq) * DHd + tn * 8 + g;
            uint2 u;
            u.x = tf32u(sp[0]);
            u.y = tf32u(sp[4 * DHd]);
            ((uint2*)bufB)[tile * 32 + lane] = u;
        }
        __syncthreads();
#pragma unroll 4
        for (int ks = 0; ks < 16; ks++) {
            uint4 af[4];
            uint2 bf[2];
#pragma unroll
            for (int mt = 0; mt < 4; mt++)
                af[mt] = ((const uint4*)bufQ)[((wm * 4 + mt) * 32 + hs * 16 + ks) * 32 + lane];
#pragma unroll
            for (int nt = 0; nt < 2; nt++)
                bf[nt] = ((const uint2*)bufB)[(ks * 8 + wn * 2 + nt) * 32 + lane];
#pragma unroll
            for (int mt = 0; mt < 4; mt++)
#pragma unroll
                for (int nt = 0; nt < 2; nt++)
                    mma16n8k8(acc2[mt][nt], (const uint32_t*)&af[mt],
                              (const uint32_t*)&bf[nt]);
        }
    }

    // ---- Write masked A into bufQ as Afrag (8 mtiles x 16 ktiles) ----
    __syncthreads();   // everyone done reading Q from bufQ
    {
        int l0 = g * 4 + ((2 * tq) & 3);
        int s0 = 2 * ((2 * tq) >> 2);
        int l1 = g * 4 + ((2 * tq + 1) & 3);
        int s1 = 2 * ((2 * tq + 1) >> 2);
#pragma unroll
        for (int mt = 0; mt < 4; mt++)
#pragma unroll
            for (int nt = 0; nt < 4; nt++) {
                int tile = (wm * 4 + mt) * 16 + wn * 4 + nt;
                float* tb = bufQ + tile * 128;
                tb[l0 * 4 + s0]     = tf32r(accA[mt][nt][0]);
                tb[l1 * 4 + s1]     = tf32r(accA[mt][nt][1]);
                tb[l0 * 4 + s0 + 1] = tf32r(accA[mt][nt][2]);
                tb[l1 * 4 + s1 + 1] = tf32r(accA[mt][nt][3]);
            }
    }
    // ---- Stage V as Bfrag: 16 ktiles x 8 ntiles ----
#pragma unroll 2
    for (int it = 0; it < 16; it++) {
        int tile = it * 8 + wid;
        int tk = tile >> 3, tn = tile & 7;
        const float* vp = vin + ((size_t)(b * NN + n0 + tk * 8 + tq)) * Dd
                        + h * DHd + tn * 8 + g;
        uint2 u;
        u.x = tf32u(vp[0]);
        u.y = tf32u(vp[4 * Dd]);
        ((uint2*)bufB)[tile * 32 + lane] = u;
    }
    __syncthreads();

    // ---- Phase 3: out += tril(A) . V (K=128) ----
#pragma unroll 4
    for (int ks = 0; ks < 16; ks++) {
        uint4 af[4];
        uint2 bf[2];
#pragma unroll
        for (int mt = 0; mt < 4; mt++)
            af[mt] = ((const uint4*)bufQ)[((wm * 4 + mt) * 16 + ks) * 32 + lane];
#pragma unroll
        for (int nt = 0; nt < 2; nt++)
            bf[nt] = ((const uint2*)bufB)[(ks * 8 + wn * 2 + nt) * 32 + lane];
#pragma unroll
        for (int mt = 0; mt < 4; mt++)
#pragma unroll
            for (int nt = 0; nt < 2; nt++)
                mma16n8k8(acc2[mt][nt], (const uint32_t*)&af[mt],
                          (const uint32_t*)&bf[nt]);
    }

    // ---- Epilogue: scale by dinv, store ----
#pragma unroll
    for (int mt = 0; mt < 4; mt++) {
        int r0 = wm * 64 + mt * 16 + g;
        float d0 = dinv[r0], d1 = dinv[r0 + 8];
        float* op0 = outp + ((size_t)(b * NN + n0 + r0)) * Dd + h * DHd;
        float* op1 = op0 + (size_t)8 * Dd;
#pragma unroll
        for (int nt = 0; nt < 2; nt++) {
            int e = wn * 16 + nt * 8 + tq * 2;
            float2 o0 = make_float2(acc2[mt][nt][0] * d0, acc2[mt][nt][1] * d0);
            float2 o1 = make_float2(acc2[mt][nt][2] * d1, acc2[mt][nt][3] * d1);
            *(float2*)(op0 + e) = o0;
            *(float2*)(op1 + e) = o1;
        }
    }
}

// ---------------------------------------------------------------------------
extern "C" void kernel_launch(void* const* d_in, const int* in_sizes, int n_in,
                              void* d_out, int out_size) {
    (void)in_sizes; (void)n_in; (void)out_size;
    const float* q    = (const float*)d_in[0];
    const float* k    = (const float*)d_in[1];
    const float* v    = (const float*)d_in[2];
    const float* proj = (const float*)d_in[3];
    float* out = (float*)d_out;

    cudaFuncSetAttribute(out_kernel, cudaFuncAttributeMaxDynamicSharedMemorySize,
                         OUT_DSMEM);

    init_kernel<<<1, 32>>>();
    feat_kernel<true><<<dim3(16, 32), 256>>>(q, proj);
    feat_kernel<false><<<dim3(16, 32), 256>>>(k, proj);
    kexp_kernel<<<16384, 256>>>();
    chunk_kv_kernel<<<dim3(16, 32), 256>>>(v);
    prefix_kernel<<<32, 256>>>();
    out_kernel<<<dim3(16, 32), 256, OUT_DSMEM>>>(v, out);
}

// round 4
// speedup vs baseline: 1.9092x; 1.6286x over previous
#include <cuda_runtime.h>
#include <math.h>
#include <stdint.h>

// Problem constants
#define Bb 4
#define Hh 8
#define BHn 32
#define NN 2048
#define Dd 512
#define DHd 64
#define MF 256
#define CK 128
#define NC 16

// Scratch
__device__ float g_qp[(size_t)BHn * NN * MF];          // 64 MiB
__device__ float g_kp[(size_t)BHn * NN * MF];          // 64 MiB
__device__ float g_S [(size_t)BHn * NC * MF * DHd];    // 32 MiB
__device__ float g_z [BHn * NC * MF];
__device__ float g_kmax[BHn];

__device__ __forceinline__ float tf32r(float x) {
    uint32_t u = __float_as_uint(x);
    u = (u + 0x1000u) & 0xFFFFE000u;
    return __uint_as_float(u);
}
__device__ __forceinline__ uint32_t tf32u(float x) {
    return (__float_as_uint(x) + 0x1000u) & 0xFFFFE000u;
}

// Warp-level tf32 MMA (portable ISA; tensor pipe)
__device__ __forceinline__ void mma16n8k8(float c[4], const uint32_t a[4],
                                          const uint32_t b[2]) {
    asm volatile(
        "mma.sync.aligned.m16n8k8.row.col.f32.tf32.tf32.f32 "
        "{%0,%1,%2,%3}, {%4,%5,%6,%7}, {%8,%9}, {%0,%1,%2,%3};"
        : "+f"(c[0]), "+f"(c[1]), "+f"(c[2]), "+f"(c[3])
        : "r"(a[0]), "r"(a[1]), "r"(a[2]), "r"(a[3]), "r"(b[0]), "r"(b[1]));
}

__global__ void init_kernel() {
    if (threadIdx.x < BHn) g_kmax[threadIdx.x] = -1e30f;
}

// ---------------------------------------------------------------------------
// Feature-map kernel on tensor cores (split-tf32, fp32-quality).
// Block: 64 rows of one bh. Warp (wm 0..3, wn 0..1): mtile wm (16 rows),
// f-half wn (128 features = 16 ntiles). dd = X . P^T, K = 64 (8 ksteps).
// X frags in registers (hi+lo), P staged per-kstep into smem as split B-frags.
// ---------------------------------------------------------------------------
template <bool IS_Q>
__global__ void __launch_bounds__(256) feat_kernel(const float* __restrict__ xin,
                                                   const float* __restrict__ proj) {
    __shared__ uint4 ps[1024];   // 16KB: [nt(32)][lane(32)] = {bhi0,bhi1,blo0,blo1}
    __shared__ float mx[64][2];
    __shared__ float bred[8];

    const int t = threadIdx.x, wid = t >> 5, lane = t & 31;
    const int g = lane >> 2, tq = lane & 3;
    const int wm = wid >> 1, wn = wid & 1;
    const int bh = blockIdx.y, b = bh >> 3, h = bh & 7;
    const int n0 = blockIdx.x * 64;
    const int r0 = n0 + wm * 16;

    // X fragments (hi/lo split) + per-row sumsq
    uint4 ah[8], al[8];
    float ss0 = 0.f, ss1 = 0.f;
    const float* xb = xin + ((size_t)b * NN + r0) * Dd + h * DHd;
#pragma unroll
    for (int ks = 0; ks < 8; ks++) {
        float x0 = xb[(size_t)g * Dd + ks * 8 + tq];
        float x1 = xb[(size_t)(g + 8) * Dd + ks * 8 + tq];
        float x2 = xb[(size_t)g * Dd + ks * 8 + tq + 4];
        float x3 = xb[(size_t)(g + 8) * Dd + ks * 8 + tq + 4];
        ss0 += x0 * x0 + x2 * x2;
        ss1 += x1 * x1 + x3 * x3;
        uint32_t h0 = __float_as_uint(x0) & 0xFFFFE000u;
        uint32_t h1 = __float_as_uint(x1) & 0xFFFFE000u;
        uint32_t h2 = __float_as_uint(x2) & 0xFFFFE000u;
        uint32_t h3 = __float_as_uint(x3) & 0xFFFFE000u;
        ah[ks] = make_uint4(h0, h1, h2, h3);
        al[ks] = make_uint4(__float_as_uint(x0 - __uint_as_float(h0)),
                            __float_as_uint(x1 - __uint_as_float(h1)),
                            __float_as_uint(x2 - __uint_as_float(h2)),
                            __float_as_uint(x3 - __uint_as_float(h3)));
    }
    ss0 += __shfl_xor_sync(0xffffffffu, ss0, 1);
    ss0 += __shfl_xor_sync(0xffffffffu, ss0, 2);
    ss1 += __shfl_xor_sync(0xffffffffu, ss1, 1);
    ss1 += __shfl_xor_sync(0xffffffffu, ss1, 2);
    const float diag0 = ss0 * 0.0625f, diag1 = ss1 * 0.0625f;

    float acc[16][4];
#pragma unroll
    for (int i = 0; i < 16; i++)
#pragma unroll
        for (int j = 0; j < 4; j++) acc[i][j] = 0.f;

    for (int ks = 0; ks < 8; ks++) {
        __syncthreads();
#pragma unroll
        for (int it = 0; it < 4; it++) {
            int slot = it * 256 + t;
            int nt = slot >> 5, sl = slot & 31;
            int sg = sl >> 2, stq = sl & 3;
            const float* pp = proj + (nt * 8 + sg) * 64 + ks * 8 + stq;
            float p0 = pp[0], p1 = pp[4];
            uint32_t h0 = __float_as_uint(p0) & 0xFFFFE000u;
            uint32_t h1 = __float_as_uint(p1) & 0xFFFFE000u;
            ps[slot] = make_uint4(h0, h1,
                                  __float_as_uint(p0 - __uint_as_float(h0)),
                                  __float_as_uint(p1 - __uint_as_float(h1)));
        }
        __syncthreads();
#pragma unroll
        for (int ntl = 0; ntl < 16; ntl++) {
            uint4 pv = ps[(wn * 16 + ntl) * 32 + lane];
            uint32_t bhi[2] = {pv.x, pv.y};
            uint32_t blo[2] = {pv.z, pv.w};
            mma16n8k8(acc[ntl], (const uint32_t*)&ah[ks], bhi);
            mma16n8k8(acc[ntl], (const uint32_t*)&al[ks], bhi);
            mma16n8k8(acc[ntl], (const uint32_t*)&ah[ks], blo);
        }
    }

    const float normalizer = 0.35355339059327373f;
#pragma unroll
    for (int ntl = 0; ntl < 16; ntl++)
#pragma unroll
        for (int j = 0; j < 4; j++) acc[ntl][j] *= normalizer;

    if (IS_Q) {
        float m0 = -1e30f, m1 = -1e30f;
#pragma unroll
        for (int ntl = 0; ntl < 16; ntl++) {
            m0 = fmaxf(m0, fmaxf(acc[ntl][0], acc[ntl][1]));
            m1 = fmaxf(m1, fmaxf(acc[ntl][2], acc[ntl][3]));
        }
        m0 = fmaxf(m0, __shfl_xor_sync(0xffffffffu, m0, 1));
        m0 = fmaxf(m0, __shfl_xor_sync(0xffffffffu, m0, 2));
        m1 = fmaxf(m1, __shfl_xor_sync(0xffffffffu, m1, 1));
        m1 = fmaxf(m1, __shfl_xor_sync(0xffffffffu, m1, 2));
        if (tq == 0) {
            mx[wm * 16 + g][wn] = m0;
            mx[wm * 16 + g + 8][wn] = m1;
        }
        __syncthreads();
        const float M0 = fmaxf(mx[wm * 16 + g][0], mx[wm * 16 + g][1]);
        const float M1 = fmaxf(mx[wm * 16 + g + 8][0], mx[wm * 16 + g + 8][1]);
        float* o0 = g_qp + ((size_t)bh * NN + r0 + g) * MF + wn * 128;
        float* o1 = g_qp + ((size_t)bh * NN + r0 + g + 8) * MF + wn * 128;
#pragma unroll
        for (int ntl = 0; ntl < 16; ntl++) {
            float2 v0, v1;
            v0.x = 0.0625f * (expf(acc[ntl][0] - diag0 - M0) + 1e-4f);
            v0.y = 0.0625f * (expf(acc[ntl][1] - diag0 - M0) + 1e-4f);
            v1.x = 0.0625f * (expf(acc[ntl][2] - diag1 - M1) + 1e-4f);
            v1.y = 0.0625f * (expf(acc[ntl][3] - diag1 - M1) + 1e-4f);
            *(float2*)(o0 + ntl * 8 + tq * 2) = v0;
            *(float2*)(o1 + ntl * 8 + tq * 2) = v1;
        }
    } else {
        float km = -1e30f;
        float* o0 = g_kp + ((size_t)bh * NN + r0 + g) * MF + wn * 128;
        float* o1 = g_kp + ((size_t)bh * NN + r0 + g + 8) * MF + wn * 128;
#pragma unroll
        for (int ntl = 0; ntl < 16; ntl++) {
            km = fmaxf(km, fmaxf(fmaxf(acc[ntl][0], acc[ntl][1]),
                                 fmaxf(acc[ntl][2], acc[ntl][3])));
            float2 v0 = make_float2(acc[ntl][0] - diag0, acc[ntl][1] - diag0);
            float2 v1 = make_float2(acc[ntl][2] - diag1, acc[ntl][3] - diag1);
            *(float2*)(o0 + ntl * 8 + tq * 2) = v0;
            *(float2*)(o1 + ntl * 8 + tq * 2) = v1;
        }
#pragma unroll
        for (int off = 16; off; off >>= 1)
            km = fmaxf(km, __shfl_xor_sync(0xffffffffu, km, off));
        if (lane == 0) bred[wid] = km;
        __syncthreads();
        if (t == 0) {
            float m = bred[0];
            for (int w = 1; w < 8; w++) m = fmaxf(m, bred[w]);
            int* addr = (int*)&g_kmax[bh];
            int old = *addr;
            while (__int_as_float(old) < m) {
                int assumed = old;
                old = atomicCAS(addr, assumed, __float_as_int(m));
                if (old == assumed) break;
            }
        }
    }
}

__global__ void __launch_bounds__(256) kexp_kernel() {
    size_t i = (size_t)blockIdx.x * 256 + threadIdx.x;
    int bh = (int)(i >> 17);
    float m = g_kmax[bh];
    float4* p = ((float4*)g_kp) + i;
    float4 v = *p;
    v.x = 0.0625f * (expf(v.x - m) + 1e-4f);
    v.y = 0.0625f * (expf(v.y - m) + 1e-4f);
    v.z = 0.0625f * (expf(v.z - m) + 1e-4f);
    v.w = 0.0625f * (expf(v.w - m) + 1e-4f);
    *p = v;
}

// ---------------------------------------------------------------------------
// Per-chunk local KV state on tensor cores (single tf32; z in fp32).
// S[m][e] = sum_j kp[j][m] V[j][e]. M=256(16mt), N=64(8nt), K=128(16ks).
// Warp wid: mtiles {2wid, 2wid+1}. Direct-LDG fragments (fully coalesced).
// ---------------------------------------------------------------------------
__global__ void __launch_bounds__(256) chunk_kv_kernel(const float* __restrict__ vin) {
    const int t = threadIdx.x, wid = t >> 5, lane = t & 31;
    const int g = lane >> 2, tq = lane & 3;
    const int c = blockIdx.x, bh = blockIdx.y;
    const int b = bh >> 3, h = bh & 7;
    const int n0 = c * CK;
    const float* kb = g_kp + (size_t)(bh * NN + n0) * MF;
    const float* vb = vin + ((size_t)(b * NN + n0)) * Dd + h * DHd;

    float acc[2][8][4];
#pragma unroll
    for (int i = 0; i < 2; i++)
#pragma unroll
        for (int n = 0; n < 8; n++)
#pragma unroll
            for (int j = 0; j < 4; j++) acc[i][n][j] = 0.f;
    float z0[2] = {0.f, 0.f}, z1[2] = {0.f, 0.f};

    for (int tk = 0; tk < 16; tk++) {
        const int j0 = tk * 8 + tq, j1 = j0 + 4;
        uint32_t af[2][4];
#pragma unroll
        for (int i = 0; i < 2; i++) {
            int m = (wid * 2 + i) * 16 + g;
            float a0 = kb[(size_t)j0 * MF + m];
            float a1 = kb[(size_t)j0 * MF + m + 8];
            float a2 = kb[(size_t)j1 * MF + m];
            float a3 = kb[(size_t)j1 * MF + m + 8];
            z0[i] += a0 + a2;
            z1[i] += a1 + a3;
            af[i][0] = tf32u(a0); af[i][1] = tf32u(a1);
            af[i][2] = tf32u(a2); af[i][3] = tf32u(a3);
        }
#pragma unroll
        for (int nt = 0; nt < 8; nt++) {
            uint32_t bf[2];
            bf[0] = tf32u(vb[(size_t)j0 * Dd + nt * 8 + g]);
            bf[1] = tf32u(vb[(size_t)j1 * Dd + nt * 8 + g]);
            mma16n8k8(acc[0][nt], af[0], bf);
            mma16n8k8(acc[1][nt], af[1], bf);
        }
    }

#pragma unroll
    for (int i = 0; i < 2; i++) {
        z0[i] += __shfl_xor_sync(0xffffffffu, z0[i], 1);
        z0[i] += __shfl_xor_sync(0xffffffffu, z0[i], 2);
        z1[i] += __shfl_xor_sync(0xffffffffu, z1[i], 1);
        z1[i] += __shfl_xor_sync(0xffffffffu, z1[i], 2);
    }
    if (tq == 0) {
        float* zp = g_z + (bh * NC + c) * MF;
#pragma unroll
        for (int i = 0; i < 2; i++) {
            int m = (wid * 2 + i) * 16 + g;
            zp[m] = z0[i];
            zp[m + 8] = z1[i];
        }
    }

    float* Sp = g_S + (size_t)(bh * NC + c) * MF * DHd;
#pragma unroll
    for (int i = 0; i < 2; i++) {
        int m = (wid * 2 + i) * 16 + g;
#pragma unroll
        for (int nt = 0; nt < 8; nt++) {
            *(float2*)(Sp + (size_t)m * DHd + nt * 8 + tq * 2) =
                make_float2(acc[i][nt][0], acc[i][nt][1]);
            *(float2*)(Sp + (size_t)(m + 8) * DHd + nt * 8 + tq * 2) =
                make_float2(acc[i][nt][2], acc[i][nt][3]);
        }
    }
}

// ---------------------------------------------------------------------------
// Fully parallel exclusive prefix over chunks (scan length NC=16 per element).
// Blocks [0,2048): g_S elements; blocks [2048,2080): g_z.
// ---------------------------------------------------------------------------
__global__ void __launch_bounds__(256) prefix_kernel() {
    const int blk = blockIdx.x;
    if (blk < 2048) {
        int idx = blk * 256 + threadIdx.x;      // 0 .. 524287
        int bh = idx >> 14;                     // 16384 elems per bh
        int me = idx & 16383;
        float* base = g_S + (size_t)bh * (NC * MF * DHd) + me;
        float run = 0.f;
#pragma unroll
        for (int c = 0; c < NC; c++) {
            float v = base[(size_t)c * (MF * DHd)];
            base[(size_t)c * (MF * DHd)] = run;
            run += v;
        }
    } else {
        int bh = blk - 2048;
        int m = threadIdx.x;
        float* zb = g_z + bh * NC * MF + m;
        float run = 0.f;
#pragma unroll
        for (int c = 0; c < NC; c++) {
            float v = zb[c * MF];
            zb[c * MF] = run;
            run += v;
        }
    }
}

// ---------------------------------------------------------------------------
// Output kernel (unchanged from round 3 — passing, rel_err 2.5e-4).
// ---------------------------------------------------------------------------
#define OUT_DSMEM (163840)

__global__ void __launch_bounds__(256) out_kernel(const float* __restrict__ vin,
                                                  float* __restrict__ outp) {
    extern __shared__ float sm[];
    float* bufQ = sm;            // 32768 floats (128KB)
    float* bufB = sm + 32768;    // 8192 floats (32KB)
    __shared__ float zs[256];
    __shared__ float den[128];
    __shared__ float den2[256];
    __shared__ float dinv[128];

    const int t = threadIdx.x, wid = t >> 5, lane = t & 31;
    const int wm = wid >> 2, wn = wid & 3;
    const int c = blockIdx.x, bh = blockIdx.y;
    const int b = bh >> 3, h = bh & 7;
    const int n0 = c * CK;
    const float* qbase = g_qp + (size_t)(bh * NN + n0) * MF;
    const float* kbase = g_kp + (size_t)(bh * NN + n0) * MF;
    const float* Sbase = g_S + (size_t)(bh * NC + c) * MF * DHd;

    zs[t] = g_z[(bh * NC + c) * MF + t];

    {
        const int g = lane >> 2, tq = lane & 3;
#pragma unroll 4
        for (int it = 0; it < 32; it++) {
            int tile = it * 8 + wid;
            int tm = tile >> 5, tk = tile & 31;
            const float* qp = qbase + (size_t)(tm * 16 + g) * MF + tk * 8 + tq;
            uint4 u;
            u.x = tf32u(qp[0]);
            u.y = tf32u(qp[8 * MF]);
            u.z = tf32u(qp[4]);
            u.w = tf32u(qp[8 * MF + 4]);
            ((uint4*)bufQ)[tile * 32 + lane] = u;
        }
    }
    __syncthreads();

    {
        int i = t >> 1, hf = t & 1;
        float s = 0.f;
        const float* qr = qbase + (size_t)i * MF + hf * 128;
        const float* zr = zs + hf * 128;
#pragma unroll 8
        for (int m = 0; m < 128; m += 4) {
            float4 q4 = *(const float4*)(qr + m);
            s += q4.x * (zr[m + 0] + 1e-6f) + q4.y * (zr[m + 1] + 1e-6f)
               + q4.z * (zr[m + 2] + 1e-6f) + q4.w * (zr[m + 3] + 1e-6f);
        }
        den2[t] = s;
    }
    __syncthreads();
    if (t < 128) den[t] = den2[2 * t] + den2[2 * t + 1];

    float accA[4][4][4];
#pragma unroll
    for (int i = 0; i < 4; i++)
#pragma unroll
        for (int j = 0; j < 4; j++)
#pragma unroll
            for (int s = 0; s < 4; s++) accA[i][j][s] = 0.f;

    const int g = lane >> 2, tq = lane & 3;
    for (int kc = 0; kc < 4; kc++) {
        __syncthreads();
#pragma unroll 2
        for (int it = 0; it < 16; it++) {
            int tile = it * 8 + wid;
            int tk = tile >> 4, tn = tile & 15;
            const float* kp = kbase + (size_t)(tn * 8 + g) * MF + kc * 64 + tk * 8 + tq;
            uint2 u;
            u.x = tf32u(kp[0]);
            u.y = tf32u(kp[4]);
            ((uint2*)bufB)[tile * 32 + lane] = u;
        }
        __syncthreads();
#pragma unroll
        for (int ks = 0; ks < 8; ks++) {
            uint4 af[4];
            uint2 bf[4];
#pragma unroll
            for (int mt = 0; mt < 4; mt++)
                af[mt] = ((const uint4*)bufQ)[((wm * 4 + mt) * 32 + kc * 8 + ks) * 32 + lane];
#pragma unroll
            for (int nt = 0; nt < 4; nt++)
                bf[nt] = ((const uint2*)bufB)[(ks * 16 + wn * 4 + nt) * 32 + lane];
#pragma unroll
            for (int mt = 0; mt < 4; mt++)
#pragma unroll
                for (int nt = 0; nt < 4; nt++)
                    mma16n8k8(accA[mt][nt], (const uint32_t*)&af[mt],
                              (const uint32_t*)&bf[nt]);
        }
    }

#pragma unroll
    for (int mt = 0; mt < 4; mt++) {
        int r0 = wm * 64 + mt * 16 + g;
        float rs0 = 0.f, rs1 = 0.f;
#pragma unroll
        for (int nt = 0; nt < 4; nt++) {
            int cb = wn * 32 + nt * 8 + tq * 2;
            float v0 = (cb     <= r0    ) ? accA[mt][nt][0] : 0.f;
            float v1 = (cb + 1 <= r0    ) ? accA[mt][nt][1] : 0.f;
            float v2 = (cb     <= r0 + 8) ? accA[mt][nt][2] : 0.f;
            float v3 = (cb + 1 <= r0 + 8) ? accA[mt][nt][3] : 0.f;
            accA[mt][nt][0] = v0; accA[mt][nt][1] = v1;
            accA[mt][nt][2] = v2; accA[mt][nt][3] = v3;
            rs0 += v0 + v1;
            rs1 += v2 + v3;
        }
        rs0 += __shfl_xor_sync(0xffffffffu, rs0, 1);
        rs0 += __shfl_xor_sync(0xffffffffu, rs0, 2);
        rs1 += __shfl_xor_sync(0xffffffffu, rs1, 1);
        rs1 += __shfl_xor_sync(0xffffffffu, rs1, 2);
        if (tq == 0) {
            atomicAdd(&den[r0], rs0);
            atomicAdd(&den[r0 + 8], rs1);
        }
    }
    __syncthreads();
    if (t < 128) dinv[t] = 1.0f / den[t];

    float acc2[4][2][4];
#pragma unroll
    for (int i = 0; i < 4; i++)
#pragma unroll
        for (int j = 0; j < 2; j++)
#pragma unroll
            for (int s = 0; s < 4; s++) acc2[i][j][s] = 0.f;

    for (int hs = 0; hs < 2; hs++) {
        __syncthreads();
#pragma unroll 2
        for (int it = 0; it < 16; it++) {
            int tile = it * 8 + wid;
            int tk = tile >> 3, tn = tile & 7;
            const float* sp = Sbase + (size_t)(hs * 128 + tk * 8 + tq) * DHd + tn * 8 + g;
            uint2 u;
            u.x = tf32u(sp[0]);
            u.y = tf32u(sp[4 * DHd]);
            ((uint2*)bufB)[tile * 32 + lane] = u;
        }
        __syncthreads();
#pragma unroll 4
        for (int ks = 0; ks < 16; ks++) {
            uint4 af[4];
            uint2 bf[2];
#pragma unroll
            for (int mt = 0; mt < 4; mt++)
                af[mt] = ((const uint4*)bufQ)[((wm * 4 + mt) * 32 + hs * 16 + ks) * 32 + lane];
#pragma unroll
            for (int nt = 0; nt < 2; nt++)
                bf[nt] = ((const uint2*)bufB)[(ks * 8 + wn * 2 + nt) * 32 + lane];
#pragma unroll
            for (int mt = 0; mt < 4; mt++)
#pragma unroll
                for (int nt = 0; nt < 2; nt++)
                    mma16n8k8(acc2[mt][nt], (const uint32_t*)&af[mt],
                              (const uint32_t*)&bf[nt]);
        }
    }

    __syncthreads();
    {
        int l0 = g * 4 + ((2 * tq) & 3);
        int s0 = 2 * ((2 * tq) >> 2);
        int l1 = g * 4 + ((2 * tq + 1) & 3);
        int s1 = 2 * ((2 * tq + 1) >> 2);
#pragma unroll
        for (int mt = 0; mt < 4; mt++)
#pragma unroll
            for (int nt = 0; nt < 4; nt++) {
                int tile = (wm * 4 + mt) * 16 + wn * 4 + nt;
                float* tb = bufQ + tile * 128;
                tb[l0 * 4 + s0]     = tf32r(accA[mt][nt][0]);
                tb[l1 * 4 + s1]     = tf32r(accA[mt][nt][1]);
                tb[l0 * 4 + s0 + 1] = tf32r(accA[mt][nt][2]);
                tb[l1 * 4 + s1 + 1] = tf32r(accA[mt][nt][3]);
            }
    }
#pragma unroll 2
    for (int it = 0; it < 16; it++) {
        int tile = it * 8 + wid;
        int tk = tile >> 3, tn = tile & 7;
        const float* vp = vin + ((size_t)(b * NN + n0 + tk * 8 + tq)) * Dd
                        + h * DHd + tn * 8 + g;
        uint2 u;
        u.x = tf32u(vp[0]);
        u.y = tf32u(vp[4 * Dd]);
        ((uint2*)bufB)[tile * 32 + lane] = u;
    }
    __syncthreads();

#pragma unroll 4
    for (int ks = 0; ks < 16; ks++) {
        uint4 af[4];
        uint2 bf[2];
#pragma unroll
        for (int mt = 0; mt < 4; mt++)
            af[mt] = ((const uint4*)bufQ)[((wm * 4 + mt) * 16 + ks) * 32 + lane];
#pragma unroll
        for (int nt = 0; nt < 2; nt++)
            bf[nt] = ((const uint2*)bufB)[(ks * 8 + wn * 2 + nt) * 32 + lane];
#pragma unroll
        for (int mt = 0; mt < 4; mt++)
#pragma unroll
            for (int nt = 0; nt < 2; nt++)
                mma16n8k8(acc2[mt][nt], (const uint32_t*)&af[mt],
                          (const uint32_t*)&bf[nt]);
    }

#pragma unroll
    for (int mt = 0; mt < 4; mt++) {
        int r0 = wm * 64 + mt * 16 + g;
        float d0 = dinv[r0], d1 = dinv[r0 + 8];
        float* op0 = outp + ((size_t)(b * NN + n0 + r0)) * Dd + h * DHd;
        float* op1 = op0 + (size_t)8 * Dd;
#pragma unroll
        for (int nt = 0; nt < 2; nt++) {
            int e = wn * 16 + nt * 8 + tq * 2;
            float2 o0 = make_float2(acc2[mt][nt][0] * d0, acc2[mt][nt][1] * d0);
            float2 o1 = make_float2(acc2[mt][nt][2] * d1, acc2[mt][nt][3] * d1);
            *(float2*)(op0 + e) = o0;
            *(float2*)(op1 + e) = o1;
        }
    }
}

// ---------------------------------------------------------------------------
extern "C" void kernel_launch(void* const* d_in, const int* in_sizes, int n_in,
                              void* d_out, int out_size) {
    (void)in_sizes; (void)n_in; (void)out_size;
    const float* q    = (const float*)d_in[0];
    const float* k    = (const float*)d_in[1];
    const float* v    = (const float*)d_in[2];
    const float* proj = (const float*)d_in[3];
    float* out = (float*)d_out;

    cudaFuncSetAttribute(out_kernel, cudaFuncAttributeMaxDynamicSharedMemorySize,
                         OUT_DSMEM);

    init_kernel<<<1, 32>>>();
    feat_kernel<true><<<dim3(32, 32), 256>>>(q, proj);
    feat_kernel<false><<<dim3(32, 32), 256>>>(k, proj);
    kexp_kernel<<<16384, 256>>>();
    chunk_kv_kernel<<<dim3(16, 32), 256>>>(v);
    prefix_kernel<<<2080, 256>>>();
    out_kernel<<<dim3(16, 32), 256, OUT_DSMEM>>>(v, out);
}

// round 5
// speedup vs baseline: 2.3941x; 1.2540x over previous
#include <cuda_runtime.h>
#include <math.h>
#include <stdint.h>

// Problem constants
#define Bb 4
#define Hh 8
#define BHn 32
#define NN 2048
#define Dd 512
#define DHd 64
#define MF 256
#define CK 128
#define NC 16

// Scratch
__device__ float g_qp[(size_t)BHn * NN * MF];          // 64 MiB
__device__ float g_kp[(size_t)BHn * NN * MF];          // 64 MiB
__device__ float g_S [(size_t)BHn * NC * MF * DHd];    // 32 MiB
__device__ float g_z [BHn * NC * MF];
__device__ float g_kmax[BHn];

__device__ __forceinline__ float tf32r(float x) {
    uint32_t u = __float_as_uint(x);
    u = (u + 0x1000u) & 0xFFFFE000u;
    return __uint_as_float(u);
}
__device__ __forceinline__ uint32_t tf32u(float x) {
    return (__float_as_uint(x) + 0x1000u) & 0xFFFFE000u;
}
__device__ __forceinline__ float4 tf32v4(float4 v) {
    v.x = tf32r(v.x); v.y = tf32r(v.y); v.z = tf32r(v.z); v.w = tf32r(v.w);
    return v;
}

// Warp-level tf32 MMA (portable ISA; tensor pipe)
__device__ __forceinline__ void mma16n8k8(float c[4], const uint32_t a[4],
                                          const uint32_t b[2]) {
    asm volatile(
        "mma.sync.aligned.m16n8k8.row.col.f32.tf32.tf32.f32 "
        "{%0,%1,%2,%3}, {%4,%5,%6,%7}, {%8,%9}, {%0,%1,%2,%3};"
        : "+f"(c[0]), "+f"(c[1]), "+f"(c[2]), "+f"(c[3])
        : "r"(a[0]), "r"(a[1]), "r"(a[2]), "r"(a[3]), "r"(b[0]), "r"(b[1]));
}

__global__ void init_kernel() {
    if (threadIdx.x < BHn) g_kmax[threadIdx.x] = -1e30f;
}

// ---------------------------------------------------------------------------
// Feature-map kernel (unchanged from round 4 — tensor-core split-tf32)
// ---------------------------------------------------------------------------
template <bool IS_Q>
__global__ void __launch_bounds__(256) feat_kernel(const float* __restrict__ xin,
                                                   const float* __restrict__ proj) {
    __shared__ uint4 ps[1024];
    __shared__ float mx[64][2];
    __shared__ float bred[8];

    const int t = threadIdx.x, wid = t >> 5, lane = t & 31;
    const int g = lane >> 2, tq = lane & 3;
    const int wm = wid >> 1, wn = wid & 1;
    const int bh = blockIdx.y, b = bh >> 3, h = bh & 7;
    const int n0 = blockIdx.x * 64;
    const int r0 = n0 + wm * 16;

    uint4 ah[8], al[8];
    float ss0 = 0.f, ss1 = 0.f;
    const float* xb = xin + ((size_t)b * NN + r0) * Dd + h * DHd;
#pragma unroll
    for (int ks = 0; ks < 8; ks++) {
        float x0 = xb[(size_t)g * Dd + ks * 8 + tq];
        float x1 = xb[(size_t)(g + 8) * Dd + ks * 8 + tq];
        float x2 = xb[(size_t)g * Dd + ks * 8 + tq + 4];
        float x3 = xb[(size_t)(g + 8) * Dd + ks * 8 + tq + 4];
        ss0 += x0 * x0 + x2 * x2;
        ss1 += x1 * x1 + x3 * x3;
        uint32_t h0 = __float_as_uint(x0) & 0xFFFFE000u;
        uint32_t h1 = __float_as_uint(x1) & 0xFFFFE000u;
        uint32_t h2 = __float_as_uint(x2) & 0xFFFFE000u;
        uint32_t h3 = __float_as_uint(x3) & 0xFFFFE000u;
        ah[ks] = make_uint4(h0, h1, h2, h3);
        al[ks] = make_uint4(__float_as_uint(x0 - __uint_as_float(h0)),
                            __float_as_uint(x1 - __uint_as_float(h1)),
                            __float_as_uint(x2 - __uint_as_float(h2)),
                            __float_as_uint(x3 - __uint_as_float(h3)));
    }
    ss0 += __shfl_xor_sync(0xffffffffu, ss0, 1);
    ss0 += __shfl_xor_sync(0xffffffffu, ss0, 2);
    ss1 += __shfl_xor_sync(0xffffffffu, ss1, 1);
    ss1 += __shfl_xor_sync(0xffffffffu, ss1, 2);
    const float diag0 = ss0 * 0.0625f, diag1 = ss1 * 0.0625f;

    float acc[16][4];
#pragma unroll
    for (int i = 0; i < 16; i++)
#pragma unroll
        for (int j = 0; j < 4; j++) acc[i][j] = 0.f;

    for (int ks = 0; ks < 8; ks++) {
        __syncthreads();
#pragma unroll
        for (int it = 0; it < 4; it++) {
            int slot = it * 256 + t;
            int nt = slot >> 5, sl = slot & 31;
            int sg = sl >> 2, stq = sl & 3;
            const float* pp = proj + (nt * 8 + sg) * 64 + ks * 8 + stq;
            float p0 = pp[0], p1 = pp[4];
            uint32_t h0 = __float_as_uint(p0) & 0xFFFFE000u;
            uint32_t h1 = __float_as_uint(p1) & 0xFFFFE000u;
            ps[slot] = make_uint4(h0, h1,
                                  __float_as_uint(p0 - __uint_as_float(h0)),
                                  __float_as_uint(p1 - __uint_as_float(h1)));
        }
        __syncthreads();
#pragma unroll
        for (int ntl = 0; ntl < 16; ntl++) {
            uint4 pv = ps[(wn * 16 + ntl) * 32 + lane];
            uint32_t bhi[2] = {pv.x, pv.y};
            uint32_t blo[2] = {pv.z, pv.w};
            mma16n8k8(acc[ntl], (const uint32_t*)&ah[ks], bhi);
            mma16n8k8(acc[ntl], (const uint32_t*)&al[ks], bhi);
            mma16n8k8(acc[ntl], (const uint32_t*)&ah[ks], blo);
        }
    }

    const float normalizer = 0.35355339059327373f;
#pragma unroll
    for (int ntl = 0; ntl < 16; ntl++)
#pragma unroll
        for (int j = 0; j < 4; j++) acc[ntl][j] *= normalizer;

    if (IS_Q) {
        float m0 = -1e30f, m1 = -1e30f;
#pragma unroll
        for (int ntl = 0; ntl < 16; ntl++) {
            m0 = fmaxf(m0, fmaxf(acc[ntl][0], acc[ntl][1]));
            m1 = fmaxf(m1, fmaxf(acc[ntl][2], acc[ntl][3]));
        }
        m0 = fmaxf(m0, __shfl_xor_sync(0xffffffffu, m0, 1));
        m0 = fmaxf(m0, __shfl_xor_sync(0xffffffffu, m0, 2));
        m1 = fmaxf(m1, __shfl_xor_sync(0xffffffffu, m1, 1));
        m1 = fmaxf(m1, __shfl_xor_sync(0xffffffffu, m1, 2));
        if (tq == 0) {
            mx[wm * 16 + g][wn] = m0;
            mx[wm * 16 + g + 8][wn] = m1;
        }
        __syncthreads();
        const float M0 = fmaxf(mx[wm * 16 + g][0], mx[wm * 16 + g][1]);
        const float M1 = fmaxf(mx[wm * 16 + g + 8][0], mx[wm * 16 + g + 8][1]);
        float* o0 = g_qp + ((size_t)bh * NN + r0 + g) * MF + wn * 128;
        float* o1 = g_qp + ((size_t)bh * NN + r0 + g + 8) * MF + wn * 128;
#pragma unroll
        for (int ntl = 0; ntl < 16; ntl++) {
            float2 v0, v1;
            v0.x = 0.0625f * (expf(acc[ntl][0] - diag0 - M0) + 1e-4f);
            v0.y = 0.0625f * (expf(acc[ntl][1] - diag0 - M0) + 1e-4f);
            v1.x = 0.0625f * (expf(acc[ntl][2] - diag1 - M1) + 1e-4f);
            v1.y = 0.0625f * (expf(acc[ntl][3] - diag1 - M1) + 1e-4f);
            *(float2*)(o0 + ntl * 8 + tq * 2) = v0;
            *(float2*)(o1 + ntl * 8 + tq * 2) = v1;
        }
    } else {
        float km = -1e30f;
        float* o0 = g_kp + ((size_t)bh * NN + r0 + g) * MF + wn * 128;
        float* o1 = g_kp + ((size_t)bh * NN + r0 + g + 8) * MF + wn * 128;
#pragma unroll
        for (int ntl = 0; ntl < 16; ntl++) {
            km = fmaxf(km, fmaxf(fmaxf(acc[ntl][0], acc[ntl][1]),
                                 fmaxf(acc[ntl][2], acc[ntl][3])));
            float2 v0 = make_float2(acc[ntl][0] - diag0, acc[ntl][1] - diag0);
            float2 v1 = make_float2(acc[ntl][2] - diag1, acc[ntl][3] - diag1);
            *(float2*)(o0 + ntl * 8 + tq * 2) = v0;
            *(float2*)(o1 + ntl * 8 + tq * 2) = v1;
        }
#pragma unroll
        for (int off = 16; off; off >>= 1)
            km = fmaxf(km, __shfl_xor_sync(0xffffffffu, km, off));
        if (lane == 0) bred[wid] = km;
        __syncthreads();
        if (t == 0) {
            float m = bred[0];
            for (int w = 1; w < 8; w++) m = fmaxf(m, bred[w]);
            int* addr = (int*)&g_kmax[bh];
            int old = *addr;
            while (__int_as_float(old) < m) {
                int assumed = old;
                old = atomicCAS(addr, assumed, __float_as_int(m));
                if (old == assumed) break;
            }
        }
    }
}

__global__ void __launch_bounds__(256) kexp_kernel() {
    size_t i = (size_t)blockIdx.x * 256 + threadIdx.x;
    int bh = (int)(i >> 17);
    float m = g_kmax[bh];
    float4* p = ((float4*)g_kp) + i;
    float4 v = *p;
    v.x = 0.0625f * (expf(v.x - m) + 1e-4f);
    v.y = 0.0625f * (expf(v.y - m) + 1e-4f);
    v.z = 0.0625f * (expf(v.z - m) + 1e-4f);
    v.w = 0.0625f * (expf(v.w - m) + 1e-4f);
    *p = v;
}

// ---------------------------------------------------------------------------
// Per-chunk local KV state (unchanged from round 4)
// ---------------------------------------------------------------------------
__global__ void __launch_bounds__(256) chunk_kv_kernel(const float* __restrict__ vin) {
    const int t = threadIdx.x, wid = t >> 5, lane = t & 31;
    const int g = lane >> 2, tq = lane & 3;
    const int c = blockIdx.x, bh = blockIdx.y;
    const int b = bh >> 3, h = bh & 7;
    const int n0 = c * CK;
    const float* kb = g_kp + (size_t)(bh * NN + n0) * MF;
    const float* vb = vin + ((size_t)(b * NN + n0)) * Dd + h * DHd;

    float acc[2][8][4];
#pragma unroll
    for (int i = 0; i < 2; i++)
#pragma unroll
        for (int n = 0; n < 8; n++)
#pragma unroll
            for (int j = 0; j < 4; j++) acc[i][n][j] = 0.f;
    float z0[2] = {0.f, 0.f}, z1[2] = {0.f, 0.f};

    for (int tk = 0; tk < 16; tk++) {
        const int j0 = tk * 8 + tq, j1 = j0 + 4;
        uint32_t af[2][4];
#pragma unroll
        for (int i = 0; i < 2; i++) {
            int m = (wid * 2 + i) * 16 + g;
            float a0 = kb[(size_t)j0 * MF + m];
            float a1 = kb[(size_t)j0 * MF + m + 8];
            float a2 = kb[(size_t)j1 * MF + m];
            float a3 = kb[(size_t)j1 * MF + m + 8];
            z0[i] += a0 + a2;
            z1[i] += a1 + a3;
            af[i][0] = tf32u(a0); af[i][1] = tf32u(a1);
            af[i][2] = tf32u(a2); af[i][3] = tf32u(a3);
        }
#pragma unroll
        for (int nt = 0; nt < 8; nt++) {
            uint32_t bf[2];
            bf[0] = tf32u(vb[(size_t)j0 * Dd + nt * 8 + g]);
            bf[1] = tf32u(vb[(size_t)j1 * Dd + nt * 8 + g]);
            mma16n8k8(acc[0][nt], af[0], bf);
            mma16n8k8(acc[1][nt], af[1], bf);
        }
    }

#pragma unroll
    for (int i = 0; i < 2; i++) {
        z0[i] += __shfl_xor_sync(0xffffffffu, z0[i], 1);
        z0[i] += __shfl_xor_sync(0xffffffffu, z0[i], 2);
        z1[i] += __shfl_xor_sync(0xffffffffu, z1[i], 1);
        z1[i] += __shfl_xor_sync(0xffffffffu, z1[i], 2);
    }
    if (tq == 0) {
        float* zp = g_z + (bh * NC + c) * MF;
#pragma unroll
        for (int i = 0; i < 2; i++) {
            int m = (wid * 2 + i) * 16 + g;
            zp[m] = z0[i];
            zp[m + 8] = z1[i];
        }
    }

    float* Sp = g_S + (size_t)(bh * NC + c) * MF * DHd;
#pragma unroll
    for (int i = 0; i < 2; i++) {
        int m = (wid * 2 + i) * 16 + g;
#pragma unroll
        for (int nt = 0; nt < 8; nt++) {
            *(float2*)(Sp + (size_t)m * DHd + nt * 8 + tq * 2) =
                make_float2(acc[i][nt][0], acc[i][nt][1]);
            *(float2*)(Sp + (size_t)(m + 8) * DHd + nt * 8 + tq * 2) =
                make_float2(acc[i][nt][2], acc[i][nt][3]);
        }
    }
}

// ---------------------------------------------------------------------------
// Fully parallel exclusive prefix (unchanged from round 4)
// ---------------------------------------------------------------------------
__global__ void __launch_bounds__(256) prefix_kernel() {
    const int blk = blockIdx.x;
    if (blk < 2048) {
        int idx = blk * 256 + threadIdx.x;
        int bh = idx >> 14;
        int me = idx & 16383;
        float* base = g_S + (size_t)bh * (NC * MF * DHd) + me;
        float run = 0.f;
#pragma unroll
        for (int c = 0; c < NC; c++) {
            float v = base[(size_t)c * (MF * DHd)];
            base[(size_t)c * (MF * DHd)] = run;
            run += v;
        }
    } else {
        int bh = blk - 2048;
        int m = threadIdx.x;
        float* zb = g_z + bh * NC * MF + m;
        float run = 0.f;
#pragma unroll
        for (int c = 0; c < NC; c++) {
            float v = zb[c * MF];
            zb[c * MF] = run;
            run += v;
        }
    }
}

// ---------------------------------------------------------------------------
// Output kernel, M=64 rows per block (grid 16 x 32 x 2), 2 CTAs/SM.
// bufA: 64x132 row-major (Q half, later masked A). pitch%32=4 -> bank 4g+tq.
// bufB0: <=128x68 (K tiles, n-row oriented). pitch%32=4 -> bank 4g+tq.
// bufB1: 128x72 (S halves / V, k-row oriented). pitch%32=8 -> bank 8tq+g.
// ---------------------------------------------------------------------------
#define PA 132
#define PB0 68
#define PB1 72
#define OFF_B0 8448                       // 64*132
#define OFF_B1 (8448 + 8704)              // + 128*68
#define OUT_DSMEM ((8448 + 8704 + 9216) * 4)

__global__ void __launch_bounds__(256, 2) out_kernel(const float* __restrict__ vin,
                                                     float* __restrict__ outp) {
    extern __shared__ float sm[];
    float* bufA = sm;
    float* bufB0 = sm + OFF_B0;
    float* bufB1 = sm + OFF_B1;
    __shared__ float den4[256];
    __shared__ float den[64];
    __shared__ float dinv[64];

    const int t = threadIdx.x, wid = t >> 5, lane = t & 31;
    const int g = lane >> 2, tq = lane & 3;
    const int wm = wid >> 2, wn = wid & 3;   // 2 x 4 warp grid
    const int c = blockIdx.x, bh = blockIdx.y, hp = blockIdx.z;
    const int b = bh >> 3, h = bh & 7;
    const int n0 = c * CK;
    const int r0c = hp * 64;                 // row offset within chunk
    const int NT1 = hp ? 4 : 2;              // phase-1 ntiles per warp
    const int njrows = hp ? 128 : 64;        // A cols / V rows needed
    const int NJT = hp ? 16 : 8;             // phase-3 ktiles

    const float* qbase = g_qp + (size_t)(bh * NN + n0 + r0c) * MF;
    const float* kbase = g_kp + (size_t)(bh * NN + n0) * MF;
    const float* Sbase = g_S + (size_t)(bh * NC + c) * MF * DHd;
    const float* zg = g_z + (bh * NC + c) * MF;

    // den partial: row i = t>>2, feature quarter t&3
    {
        int i = t >> 2, qq = t & 3;
        float s = 0.f;
        const float* qr = qbase + (size_t)i * MF + qq * 64;
        const float* zr = zg + qq * 64;
#pragma unroll 4
        for (int m = 0; m < 64; m += 4) {
            float4 q4 = *(const float4*)(qr + m);
            s += q4.x * (zr[m + 0] + 1e-6f) + q4.y * (zr[m + 1] + 1e-6f)
               + q4.z * (zr[m + 2] + 1e-6f) + q4.w * (zr[m + 3] + 1e-6f);
        }
        den4[t] = s;
    }

    float accA[2][4][4];
#pragma unroll
    for (int i = 0; i < 2; i++)
#pragma unroll
        for (int j = 0; j < 4; j++)
#pragma unroll
            for (int s = 0; s < 4; s++) accA[i][j][s] = 0.f;
    float acc2[2][2][4];
#pragma unroll
    for (int i = 0; i < 2; i++)
#pragma unroll
        for (int j = 0; j < 2; j++)
#pragma unroll
            for (int s = 0; s < 4; s++) acc2[i][j][s] = 0.f;

    const int kIters = hp ? 8 : 4;  // float4 iters for K/V staging

#pragma unroll 1
    for (int hf = 0; hf < 2; hf++) {
        if (hf) __syncthreads();  // protect bufA/B0/B1 from previous readers
        // Stage Q half hf -> bufA (64 x 128)
#pragma unroll
        for (int it = 0; it < 8; it++) {
            int idx = it * 256 + t;
            int row = idx >> 5, c4 = idx & 31;
            float4 v = *(const float4*)(qbase + (size_t)row * MF + hf * 128 + c4 * 4);
            *(float4*)(bufA + row * PA + c4 * 4) = tf32v4(v);
        }
        // Stage K chunk kc=2*hf -> bufB0 (njrows x 64)
        for (int it = 0; it < kIters; it++) {
            int idx = it * 256 + t;
            int row = idx >> 4, c4 = idx & 15;
            float4 v = *(const float4*)(kbase + (size_t)row * MF + (2 * hf) * 64 + c4 * 4);
            *(float4*)(bufB0 + row * PB0 + c4 * 4) = tf32v4(v);
        }
        // Stage S half hf -> bufB1 (128 x 64)
#pragma unroll
        for (int it = 0; it < 8; it++) {
            int idx = it * 256 + t;
            int row = idx >> 4, c4 = idx & 15;
            float4 v = *(const float4*)(Sbase + (size_t)(hf * 128 + row) * DHd + c4 * 4);
            *(float4*)(bufB1 + row * PB1 + c4 * 4) = tf32v4(v);
        }
        __syncthreads();
        if (hf == 0 && t < 64)
            den[t] = den4[4 * t] + den4[4 * t + 1] + den4[4 * t + 2] + den4[4 * t + 3];

        // Phase 1 (kc = 2*hf): bufA cols 0..63
#pragma unroll
        for (int ks = 0; ks < 8; ks++) {
            uint32_t af[2][4];
#pragma unroll
            for (int mt = 0; mt < 2; mt++) {
                const float* ap = bufA + (wm * 32 + mt * 16 + g) * PA + ks * 8 + tq;
                af[mt][0] = __float_as_uint(ap[0]);
                af[mt][1] = __float_as_uint(ap[8 * PA]);
                af[mt][2] = __float_as_uint(ap[4]);
                af[mt][3] = __float_as_uint(ap[8 * PA + 4]);
            }
#pragma unroll
            for (int nt = 0; nt < 4; nt++) {
                if (nt >= NT1) break;
                const float* bp = bufB0 + ((wn * NT1 + nt) * 8 + g) * PB0 + ks * 8 + tq;
                uint32_t bf[2] = {__float_as_uint(bp[0]), __float_as_uint(bp[4])};
                mma16n8k8(accA[0][nt], af[0], bf);
                mma16n8k8(accA[1][nt], af[1], bf);
            }
        }
        // Phase 2 (S half hf): K = 128 over bufA cols 0..127
#pragma unroll 2
        for (int ks = 0; ks < 16; ks++) {
            uint32_t af[2][4];
#pragma unroll
            for (int mt = 0; mt < 2; mt++) {
                const float* ap = bufA + (wm * 32 + mt * 16 + g) * PA + ks * 8 + tq;
                af[mt][0] = __float_as_uint(ap[0]);
                af[mt][1] = __float_as_uint(ap[8 * PA]);
                af[mt][2] = __float_as_uint(ap[4]);
                af[mt][3] = __float_as_uint(ap[8 * PA + 4]);
            }
#pragma unroll
            for (int nt = 0; nt < 2; nt++) {
                const float* bp = bufB1 + (ks * 8 + tq) * PB1 + (wn * 2 + nt) * 8 + g;
                uint32_t bf[2] = {__float_as_uint(bp[0]), __float_as_uint(bp[4 * PB1])};
                mma16n8k8(acc2[0][nt], af[0], bf);
                mma16n8k8(acc2[1][nt], af[1], bf);
            }
        }
        __syncthreads();
        // Stage K chunk kc=2*hf+1 -> bufB0
        for (int it = 0; it < kIters; it++) {
            int idx = it * 256 + t;
            int row = idx >> 4, c4 = idx & 15;
            float4 v = *(const float4*)(kbase + (size_t)row * MF + (2 * hf + 1) * 64 + c4 * 4);
            *(float4*)(bufB0 + row * PB0 + c4 * 4) = tf32v4(v);
        }
        __syncthreads();
        // Phase 1 (kc = 2*hf+1): bufA cols 64..127
#pragma unroll
        for (int ks = 0; ks < 8; ks++) {
            uint32_t af[2][4];
#pragma unroll
            for (int mt = 0; mt < 2; mt++) {
                const float* ap = bufA + (wm * 32 + mt * 16 + g) * PA + 64 + ks * 8 + tq;
                af[mt][0] = __float_as_uint(ap[0]);
                af[mt][1] = __float_as_uint(ap[8 * PA]);
                af[mt][2] = __float_as_uint(ap[4]);
                af[mt][3] = __float_as_uint(ap[8 * PA + 4]);
            }
#pragma unroll
            for (int nt = 0; nt < 4; nt++) {
                if (nt >= NT1) break;
                const float* bp = bufB0 + ((wn * NT1 + nt) * 8 + g) * PB0 + ks * 8 + tq;
                uint32_t bf[2] = {__float_as_uint(bp[0]), __float_as_uint(bp[4])};
                mma16n8k8(accA[0][nt], af[0], bf);
                mma16n8k8(accA[1][nt], af[1], bf);
            }
        }
    }

    // ---- Mask tril + rowsum -> den ----
#pragma unroll
    for (int mt = 0; mt < 2; mt++) {
        int i0 = wm * 32 + mt * 16 + g;          // local row
        int lim0 = r0c + i0, lim1 = lim0 + 8;
        float rs0 = 0.f, rs1 = 0.f;
#pragma unroll
        for (int nt = 0; nt < 4; nt++) {
            if (nt >= NT1) break;
            int cb = (wn * NT1 + nt) * 8 + tq * 2;
            float v0 = (cb     <= lim0) ? accA[mt][nt][0] : 0.f;
            float v1 = (cb + 1 <= lim0) ? accA[mt][nt][1] : 0.f;
            float v2 = (cb     <= lim1) ? accA[mt][nt][2] : 0.f;
            float v3 = (cb + 1 <= lim1) ? accA[mt][nt][3] : 0.f;
            accA[mt][nt][0] = v0; accA[mt][nt][1] = v1;
            accA[mt][nt][2] = v2; accA[mt][nt][3] = v3;
            rs0 += v0 + v1;
            rs1 += v2 + v3;
        }
        rs0 += __shfl_xor_sync(0xffffffffu, rs0, 1);
        rs0 += __shfl_xor_sync(0xffffffffu, rs0, 2);
        rs1 += __shfl_xor_sync(0xffffffffu, rs1, 1);
        rs1 += __shfl_xor_sync(0xffffffffu, rs1, 2);
        if (tq == 0) {
            atomicAdd(&den[i0], rs0);
            atomicAdd(&den[i0 + 8], rs1);
        }
    }
    __syncthreads();   // bufA free (phase1/2 done), den complete

    // ---- Store masked A into bufA row-major; stage V -> bufB1; dinv ----
    if (t < 64) dinv[t] = 1.0f / den[t];
#pragma unroll
    for (int mt = 0; mt < 2; mt++) {
        int i0 = wm * 32 + mt * 16 + g;
#pragma unroll
        for (int nt = 0; nt < 4; nt++) {
            if (nt >= NT1) break;
            int j = (wn * NT1 + nt) * 8 + tq * 2;
            *(float2*)(bufA + i0 * PA + j) =
                make_float2(tf32r(accA[mt][nt][0]), tf32r(accA[mt][nt][1]));
            *(float2*)(bufA + (i0 + 8) * PA + j) =
                make_float2(tf32r(accA[mt][nt][2]), tf32r(accA[mt][nt][3]));
        }
    }
    for (int it = 0; it < kIters; it++) {
        int idx = it * 256 + t;
        int row = idx >> 4, c4 = idx & 15;
        float4 v = *(const float4*)(vin + ((size_t)(b * NN + n0 + row)) * Dd
                                    + h * DHd + c4 * 4);
        *(float4*)(bufB1 + row * PB1 + c4 * 4) = tf32v4(v);
    }
    __syncthreads();

    // ---- Phase 3: out += tril(A) . V ----
#pragma unroll 2
    for (int ks = 0; ks < 16; ks++) {
        if (ks >= NJT) break;
        uint32_t af[2][4];
#pragma unroll
        for (int mt = 0; mt < 2; mt++) {
            const float* ap = bufA + (wm * 32 + mt * 16 + g) * PA + ks * 8 + tq;
            af[mt][0] = __float_as_uint(ap[0]);
            af[mt][1] = __float_as_uint(ap[8 * PA]);
            af[mt][2] = __float_as_uint(ap[4]);
            af[mt][3] = __float_as_uint(ap[8 * PA + 4]);
        }
#pragma unroll
        for (int nt = 0; nt < 2; nt++) {
            const float* bp = bufB1 + (ks * 8 + tq) * PB1 + (wn * 2 + nt) * 8 + g;
            uint32_t bf[2] = {__float_as_uint(bp[0]), __float_as_uint(bp[4 * PB1])};
            mma16n8k8(acc2[0][nt], af[0], bf);
            mma16n8k8(acc2[1][nt], af[1], bf);
        }
    }

    // ---- Epilogue ----
#pragma unroll
    for (int mt = 0; mt < 2; mt++) {
        int i0 = wm * 32 + mt * 16 + g;
        float d0 = dinv[i0], d1 = dinv[i0 + 8];
        float* op0 = outp + ((size_t)(b * NN + n0 + r0c + i0)) * Dd + h * DHd;
        float* op1 = op0 + (size_t)8 * Dd;
#pragma unroll
        for (int nt = 0; nt < 2; nt++) {
            int e = (wn * 2 + nt) * 8 + tq * 2;
            *(float2*)(op0 + e) = make_float2(acc2[mt][nt][0] * d0,
                                              acc2[mt][nt][1] * d0);
            *(float2*)(op1 + e) = make_float2(acc2[mt][nt][2] * d1,
                                              acc2[mt][nt][3] * d1);
        }
    }
}

// ---------------------------------------------------------------------------
extern "C" void kernel_launch(void* const* d_in, const int* in_sizes, int n_in,
                              void* d_out, int out_size) {
    (void)in_sizes; (void)n_in; (void)out_size;
    const float* q    = (const float*)d_in[0];
    const float* k    = (const float*)d_in[1];
    const float* v    = (const float*)d_in[2];
    const float* proj = (const float*)d_in[3];
    float* out = (float*)d_out;

    cudaFuncSetAttribute(out_kernel, cudaFuncAttributeMaxDynamicSharedMemorySize,
                         OUT_DSMEM);

    init_kernel<<<1, 32>>>();
    feat_kernel<true><<<dim3(32, 32), 256>>>(q, proj);
    feat_kernel<false><<<dim3(32, 32), 256>>>(k, proj);
    kexp_kernel<<<16384, 256>>>();
    chunk_kv_kernel<<<dim3(16, 32), 256>>>(v);
    prefix_kernel<<<2080, 256>>>();
    out_kernel<<<dim3(16, 32, 2), 256, OUT_DSMEM>>>(v, out);
}